// round 15
// baseline (speedup 1.0000x reference)
#include <cuda_runtime.h>
#include <cuda_fp16.h>
#include <cstdint>

// ============================================================================
// GroupFC: out[32768,1024] = data @ W^T + b (fp32), sm_103-compatible.
// R15: R14 ldmatrix skeleton widened to CTA tile 128x256 (256 thr, 8 warps,
//      64x64 warp tiles). Crossbar ratio 83%->74% of tensor window, sync cost
//      halved per tensor work, A DRAM traffic halved. 144KB smem, 1 CTA/SM.
//  - prep_A / prep_W: fp32 -> fp16 RN (DRAM-roofline).
//  - swizzle: 16B unit u of row r at u ^ (r&7); ldmatrix.m8n8.x4 feeding.
// ============================================================================

#define BATCH   32768
#define IN_DIM  1024
#define OUT_DIM 1024

#define BM 128
#define BN 256
#define KC 64                           // fp16 k per chunk (128 B per row)
#define NCHUNK (IN_DIM / KC)            // 16
#define NST 3

#define ROW_B       128
#define A_TILE      (BM * ROW_B)        // 16384
#define B_TILE      (BN * ROW_B)        // 32768
#define STAGE_BYTES (A_TILE + B_TILE)   // 49152
#define SMEM_TOTAL  (NST * STAGE_BYTES) // 147456 -> 1 CTA/SM

// fp16 copies (RN-rounded), static device scratch
__device__ __half g_Ah[(size_t)BATCH * IN_DIM];    // 64 MB
__device__ __half g_Wh[(size_t)OUT_DIM * IN_DIM];  // 2 MB

// ---------------------------------------------------------------- helpers
__device__ __forceinline__ void cp16(uint32_t dst, const void* src) {
    asm volatile("cp.async.cg.shared.global [%0], [%1], 16;"
                 :: "r"(dst), "l"(src));
}
#define CP_COMMIT() asm volatile("cp.async.commit_group;" ::: "memory")
#define CP_WAIT_1() asm volatile("cp.async.wait_group 1;" ::: "memory")

__device__ __forceinline__ uint32_t smem_u32(const void* p) {
    uint32_t a;
    asm("{ .reg .u64 t; cvta.to.shared.u64 t, %1; cvt.u32.u64 %0, t; }"
        : "=r"(a) : "l"(p));
    return a;
}

#define LDSM4(r0, r1, r2, r3, addr)                                           \
    asm volatile("ldmatrix.sync.aligned.m8n8.x4.shared.b16 {%0,%1,%2,%3}, [%4];" \
                 : "=r"(r0), "=r"(r1), "=r"(r2), "=r"(r3) : "r"(addr))

__device__ __forceinline__ void mma16(float* c,
                                      uint32_t a0, uint32_t a1, uint32_t a2, uint32_t a3,
                                      uint32_t b0, uint32_t b1) {
    asm volatile(
        "mma.sync.aligned.m16n8k16.row.col.f32.f16.f16.f32 "
        "{%0,%1,%2,%3}, {%4,%5,%6,%7}, {%8,%9}, {%0,%1,%2,%3};"
        : "+f"(c[0]), "+f"(c[1]), "+f"(c[2]), "+f"(c[3])
        : "r"(a0), "r"(a1), "r"(a2), "r"(a3), "r"(b0), "r"(b1));
}

// ---------------------------------------------------------------- prep
__device__ __forceinline__ void cvt8(const float4* __restrict__ src,
                                     uint4* __restrict__ dst, size_t i8) {
    float4 v0 = src[i8 * 2];
    float4 v1 = src[i8 * 2 + 1];
    __half2 h0 = __float22half2_rn(make_float2(v0.x, v0.y));
    __half2 h1 = __float22half2_rn(make_float2(v0.z, v0.w));
    __half2 h2 = __float22half2_rn(make_float2(v1.x, v1.y));
    __half2 h3 = __float22half2_rn(make_float2(v1.z, v1.w));
    uint4 o;
    o.x = *reinterpret_cast<uint32_t*>(&h0);
    o.y = *reinterpret_cast<uint32_t*>(&h1);
    o.z = *reinterpret_cast<uint32_t*>(&h2);
    o.w = *reinterpret_cast<uint32_t*>(&h3);
    dst[i8] = o;
}

__global__ void __launch_bounds__(256) prep_A_kernel(const float4* __restrict__ src) {
    const size_t i8 = (size_t)blockIdx.x * blockDim.x + threadIdx.x;
    cvt8(src, reinterpret_cast<uint4*>(g_Ah), i8);
}
__global__ void __launch_bounds__(256) prep_W_kernel(const float4* __restrict__ src) {
    const size_t i8 = (size_t)blockIdx.x * blockDim.x + threadIdx.x;
    cvt8(src, reinterpret_cast<uint4*>(g_Wh), i8);
}

// ---------------------------------------------------------------- GEMM
// grid = (32768/128) * (1024/256) = 256 * 4 = 1024 CTAs, 256 threads.
// nt inner: 4 consecutive CTAs share one A stripe in L2.
extern "C" __global__ void __launch_bounds__(256, 1)
groupfc_f16_kernel(const float* __restrict__ bias, float* __restrict__ out) {
    extern __shared__ char smem[];
    const uint32_t sb = smem_u32(smem);

    const int tid  = threadIdx.x;
    const int wid  = tid >> 5;          // 0..7
    const int lane = tid & 31;
    const int g    = lane >> 2;
    const int t    = lane & 3;
    const int wm   = wid >> 2;          // 0..1
    const int wn   = wid & 3;           // 0..3

    const int mt = blockIdx.x >> 2;
    const int nt = blockIdx.x & 3;
    const int m0 = mt * BM;
    const int n0 = nt * BN;

    // ldmatrix per-lane geometry (same as R14)
    const int e  = lane & 7;
    const int q3 = (lane >> 3) & 1;
    const int q4 = (lane >> 4) & 1;
    const int rA = wm * 64 + q3 * 8 + e;
    const int rB = wn * 64 + q4 * 8 + e;

    // staging: thread owns 16B unit ech of rows erow+32i (A: i<4, B: i<8).
    // swizzle: unit u of row r at u ^ (r&7); (erow+32i)&7 == erow&7.
    const int erow = tid >> 3;          // 0..31
    const int ech  = tid & 7;
    const uint32_t swz = (uint32_t)((ech ^ (erow & 7)) << 4);
    const __half* gA = g_Ah + (size_t)(m0 + erow) * IN_DIM + ech * 8;
    const __half* gW = g_Wh + (size_t)(n0 + erow) * IN_DIM + ech * 8;
    const uint32_t sdA = sb + (uint32_t)erow * ROW_B + swz;
    const uint32_t sdB = sb + A_TILE + (uint32_t)erow * ROW_B + swz;

    float c[4][8][4];
#pragma unroll
    for (int mi = 0; mi < 4; mi++)
#pragma unroll
        for (int ni = 0; ni < 8; ni++)
#pragma unroll
            for (int j = 0; j < 4; j++) c[mi][ni][j] = 0.0f;

#define FILL(cc, s)                                                           \
    do {                                                                      \
        const uint32_t _o = (uint32_t)(s) * STAGE_BYTES;                      \
        const __half* _pa = gA + (size_t)(cc) * KC;                           \
        const __half* _pw = gW + (size_t)(cc) * KC;                           \
        _Pragma("unroll")                                                     \
        for (int _i = 0; _i < 4; _i++)                                        \
            cp16(sdA + _o + _i * 32 * ROW_B, _pa + (size_t)_i * 32 * IN_DIM); \
        _Pragma("unroll")                                                     \
        for (int _i = 0; _i < 8; _i++)                                        \
            cp16(sdB + _o + _i * 32 * ROW_B, _pw + (size_t)_i * 32 * IN_DIM); \
    } while (0)

    FILL(0, 0); CP_COMMIT();
    FILL(1, 1); CP_COMMIT();

#pragma unroll 1
    for (int cc = 0; cc < NCHUNK; cc++) {
        CP_WAIT_1();
        __syncthreads();

        const int s = cc % NST;
        const uint32_t paA = sb + (uint32_t)s * STAGE_BYTES + (uint32_t)rA * ROW_B;
        const uint32_t paB = sb + (uint32_t)s * STAGE_BYTES + A_TILE
                           + (uint32_t)rB * ROW_B;

#pragma unroll
        for (int ks = 0; ks < 4; ks++) {
            const uint32_t offA = (uint32_t)(((2 * ks + q4) ^ e) << 4);
            const uint32_t offB = (uint32_t)(((2 * ks + q3) ^ e) << 4);

            // B: 4x LDSM.x4 -> (b0,b1) for ni = 2p, 2p+1
            uint32_t bb[8][2];
#pragma unroll
            for (int p = 0; p < 4; p++)
                LDSM4(bb[2 * p][0], bb[2 * p][1], bb[2 * p + 1][0], bb[2 * p + 1][1],
                      paB + (uint32_t)p * 16 * ROW_B + offB);

#pragma unroll
            for (int mi = 0; mi < 4; mi++) {
                uint32_t a0, a1, a2, a3;
                LDSM4(a0, a1, a2, a3, paA + (uint32_t)mi * 16 * ROW_B + offA);
#pragma unroll
                for (int ni = 0; ni < 8; ni++)
                    mma16(c[mi][ni], a0, a1, a2, a3, bb[ni][0], bb[ni][1]);
            }
        }

        if (cc + 2 < NCHUNK) { FILL(cc + 2, (cc + 2) % NST); }
        CP_COMMIT();
    }

    // ---- epilogue: bias add + float2 stores
#pragma unroll
    for (int mi = 0; mi < 4; mi++) {
        const int r = m0 + wm * 64 + mi * 16 + g;
        float* o0 = out + (size_t)r * OUT_DIM + n0 + wn * 64 + 2 * t;
        float* o1 = o0 + 8 * OUT_DIM;
#pragma unroll
        for (int ni = 0; ni < 8; ni++) {
            const int col = n0 + wn * 64 + ni * 8 + 2 * t;
            const float b0v = __ldg(bias + col);
            const float b1v = __ldg(bias + col + 1);
            *(float2*)(o0 + ni * 8) = make_float2(c[mi][ni][0] + b0v, c[mi][ni][1] + b1v);
            *(float2*)(o1 + ni * 8) = make_float2(c[mi][ni][2] + b0v, c[mi][ni][3] + b1v);
        }
    }
}

// ---------------------------------------------------------------- launch
extern "C" void kernel_launch(void* const* d_in, const int* in_sizes, int n_in,
                              void* d_out, int out_size) {
    const float* A    = (const float*)d_in[0];
    const float* W    = (const float*)d_in[1];
    const float* bias = (const float*)d_in[2];
    float* out = (float*)d_out;
    (void)in_sizes; (void)n_in; (void)out_size;

    cudaFuncSetAttribute(groupfc_f16_kernel,
                         cudaFuncAttributeMaxDynamicSharedMemorySize, SMEM_TOTAL);

    prep_A_kernel<<<16384, 256>>>(reinterpret_cast<const float4*>(A));
    prep_W_kernel<<<512, 256>>>(reinterpret_cast<const float4*>(W));

    const int grid = (BATCH / BM) * (OUT_DIM / BN);  // 1024
    groupfc_f16_kernel<<<grid, 256, SMEM_TOTAL>>>(bias, out);
}

// round 16
// speedup vs baseline: 1.1192x; 1.1192x over previous
#include <cuda_runtime.h>
#include <cuda_fp16.h>
#include <cstdint>

// ============================================================================
// GroupFC: out[32768,1024] = data @ W^T + b (fp32), sm_103-compatible.
// R16: R14 (split prep, fp16 m16n8k16, ldmatrix feed, 128x128 CTA, 2 CTA/SM)
//      + kslice-level LDSM double-buffering: prefetch ks+1 fragments (8 LDSM)
//      while ks's 128 MMAs execute -> overlap the crossbar burst (~256cyc)
//      under the tensor burst (~232cyc) instead of serializing.
//      + bias hoisted out of the epilogue mi-loop.
// ============================================================================

#define BATCH   32768
#define IN_DIM  1024
#define OUT_DIM 1024

#define BM 128
#define BN 128
#define KC 64                           // fp16 k per chunk (128 B per row)
#define NCHUNK (IN_DIM / KC)            // 16
#define NST 3

#define ROW_B       128
#define TILE_BYTES  (128 * ROW_B)       // 16384
#define STAGE_BYTES (2 * TILE_BYTES)    // A tile + B tile
#define SMEM_TOTAL  (NST * STAGE_BYTES) // 98304 -> 2 CTAs/SM

// fp16 copies (RN-rounded), static device scratch
__device__ __half g_Ah[(size_t)BATCH * IN_DIM];    // 64 MB
__device__ __half g_Wh[(size_t)OUT_DIM * IN_DIM];  // 2 MB

// ---------------------------------------------------------------- helpers
__device__ __forceinline__ void cp16(uint32_t dst, const void* src) {
    asm volatile("cp.async.cg.shared.global [%0], [%1], 16;"
                 :: "r"(dst), "l"(src));
}
#define CP_COMMIT() asm volatile("cp.async.commit_group;" ::: "memory")
#define CP_WAIT_1() asm volatile("cp.async.wait_group 1;" ::: "memory")

__device__ __forceinline__ uint32_t smem_u32(const void* p) {
    uint32_t a;
    asm("{ .reg .u64 t; cvta.to.shared.u64 t, %1; cvt.u32.u64 %0, t; }"
        : "=r"(a) : "l"(p));
    return a;
}

#define LDSM4(r0, r1, r2, r3, addr)                                           \
    asm volatile("ldmatrix.sync.aligned.m8n8.x4.shared.b16 {%0,%1,%2,%3}, [%4];" \
                 : "=r"(r0), "=r"(r1), "=r"(r2), "=r"(r3) : "r"(addr))

__device__ __forceinline__ void mma16(float* c,
                                      uint32_t a0, uint32_t a1, uint32_t a2, uint32_t a3,
                                      uint32_t b0, uint32_t b1) {
    asm volatile(
        "mma.sync.aligned.m16n8k16.row.col.f32.f16.f16.f32 "
        "{%0,%1,%2,%3}, {%4,%5,%6,%7}, {%8,%9}, {%0,%1,%2,%3};"
        : "+f"(c[0]), "+f"(c[1]), "+f"(c[2]), "+f"(c[3])
        : "r"(a0), "r"(a1), "r"(a2), "r"(a3), "r"(b0), "r"(b1));
}

// ---------------------------------------------------------------- prep
__device__ __forceinline__ void cvt8(const float4* __restrict__ src,
                                     uint4* __restrict__ dst, size_t i8) {
    float4 v0 = src[i8 * 2];
    float4 v1 = src[i8 * 2 + 1];
    __half2 h0 = __float22half2_rn(make_float2(v0.x, v0.y));
    __half2 h1 = __float22half2_rn(make_float2(v0.z, v0.w));
    __half2 h2 = __float22half2_rn(make_float2(v1.x, v1.y));
    __half2 h3 = __float22half2_rn(make_float2(v1.z, v1.w));
    uint4 o;
    o.x = *reinterpret_cast<uint32_t*>(&h0);
    o.y = *reinterpret_cast<uint32_t*>(&h1);
    o.z = *reinterpret_cast<uint32_t*>(&h2);
    o.w = *reinterpret_cast<uint32_t*>(&h3);
    dst[i8] = o;
}

__global__ void __launch_bounds__(256) prep_A_kernel(const float4* __restrict__ src) {
    const size_t i8 = (size_t)blockIdx.x * blockDim.x + threadIdx.x;
    cvt8(src, reinterpret_cast<uint4*>(g_Ah), i8);
}
__global__ void __launch_bounds__(256) prep_W_kernel(const float4* __restrict__ src) {
    const size_t i8 = (size_t)blockIdx.x * blockDim.x + threadIdx.x;
    cvt8(src, reinterpret_cast<uint4*>(g_Wh), i8);
}

// ---------------------------------------------------------------- GEMM
// grid = 256 * 8 = 2048 CTAs, 128 threads. nt inner: 8 CTAs share an A stripe.
extern "C" __global__ void __launch_bounds__(128, 2)
groupfc_f16_kernel(const float* __restrict__ bias, float* __restrict__ out) {
    extern __shared__ char smem[];
    const uint32_t sb = smem_u32(smem);

    const int tid  = threadIdx.x;
    const int wid  = tid >> 5;
    const int lane = tid & 31;
    const int g    = lane >> 2;
    const int t    = lane & 3;
    const int wm   = wid >> 1;
    const int wn   = wid & 1;

    const int mt = blockIdx.x >> 3;
    const int nt = blockIdx.x & 7;
    const int m0 = mt * BM;
    const int n0 = nt * BN;

    // ldmatrix per-lane geometry (same as R14)
    const int e  = lane & 7;
    const int q3 = (lane >> 3) & 1;
    const int q4 = (lane >> 4) & 1;
    const int rA = wm * 64 + q3 * 8 + e;
    const int rB = wn * 64 + q4 * 8 + e;

    // staging: thread fills 16B unit ech of rows erow+16i (i<8).
    // swizzle: unit u of row r stored at u ^ (r&7).
    const int erow = tid >> 3;          // 0..15
    const int ech  = tid & 7;
    const uint32_t swz = (uint32_t)((ech ^ (erow & 7)) << 4);
    const __half* gA = g_Ah + (size_t)(m0 + erow) * IN_DIM + ech * 8;
    const __half* gW = g_Wh + (size_t)(n0 + erow) * IN_DIM + ech * 8;
    const uint32_t sdA = sb + (uint32_t)erow * ROW_B + swz;
    const uint32_t sdB = sdA + TILE_BYTES;

    float c[4][8][4];
#pragma unroll
    for (int mi = 0; mi < 4; mi++)
#pragma unroll
        for (int ni = 0; ni < 8; ni++)
#pragma unroll
            for (int j = 0; j < 4; j++) c[mi][ni][j] = 0.0f;

#define FILL(cc, s)                                                           \
    do {                                                                      \
        const uint32_t _o = (uint32_t)(s) * STAGE_BYTES;                      \
        const __half* _pa = gA + (size_t)(cc) * KC;                           \
        const __half* _pw = gW + (size_t)(cc) * KC;                           \
        _Pragma("unroll")                                                     \
        for (int _i = 0; _i < 8; _i++) {                                      \
            cp16(sdA + _o + _i * 16 * ROW_B, _pa + (size_t)_i * 16 * IN_DIM); \
            cp16(sdB + _o + _i * 16 * ROW_B, _pw + (size_t)_i * 16 * IN_DIM); \
        }                                                                     \
    } while (0)

    // load all fragments of kslice ks into buffer buf (8 LDSM.x4)
#define LOADF(buf, ks)                                                        \
    do {                                                                      \
        const uint32_t _oa = (uint32_t)(((2 * (ks) + q4) ^ e) << 4);          \
        const uint32_t _ob = (uint32_t)(((2 * (ks) + q3) ^ e) << 4);          \
        _Pragma("unroll")                                                     \
        for (int _p = 0; _p < 4; _p++)                                        \
            LDSM4(bb[buf][2 * _p][0], bb[buf][2 * _p][1],                     \
                  bb[buf][2 * _p + 1][0], bb[buf][2 * _p + 1][1],             \
                  paB + (uint32_t)_p * 16 * ROW_B + _ob);                     \
        _Pragma("unroll")                                                     \
        for (int _mi = 0; _mi < 4; _mi++)                                     \
            LDSM4(aa[buf][_mi][0], aa[buf][_mi][1],                           \
                  aa[buf][_mi][2], aa[buf][_mi][3],                           \
                  paA + (uint32_t)_mi * 16 * ROW_B + _oa);                    \
    } while (0)

    FILL(0, 0); CP_COMMIT();
    FILL(1, 1); CP_COMMIT();

#pragma unroll 1
    for (int cc = 0; cc < NCHUNK; cc++) {
        CP_WAIT_1();
        __syncthreads();

        const int s = cc % NST;
        const uint32_t paA = sb + (uint32_t)s * STAGE_BYTES + (uint32_t)rA * ROW_B;
        const uint32_t paB = sb + (uint32_t)s * STAGE_BYTES + TILE_BYTES
                           + (uint32_t)rB * ROW_B;

        uint32_t aa[2][4][4];
        uint32_t bb[2][8][2];

        LOADF(0, 0);

#pragma unroll
        for (int ks = 0; ks < 4; ks++) {
            const int cur = ks & 1;
            if (ks < 3) LOADF(1 - cur, ks + 1);
#pragma unroll
            for (int mi = 0; mi < 4; mi++)
#pragma unroll
                for (int ni = 0; ni < 8; ni++)
                    mma16(c[mi][ni],
                          aa[cur][mi][0], aa[cur][mi][1],
                          aa[cur][mi][2], aa[cur][mi][3],
                          bb[cur][ni][0], bb[cur][ni][1]);
        }

        if (cc + 2 < NCHUNK) { FILL(cc + 2, (cc + 2) % NST); }
        CP_COMMIT();
    }

    // ---- epilogue: bias hoisted, float2 stores
    float bv[8][2];
#pragma unroll
    for (int ni = 0; ni < 8; ni++) {
        const int col = n0 + wn * 64 + ni * 8 + 2 * t;
        bv[ni][0] = __ldg(bias + col);
        bv[ni][1] = __ldg(bias + col + 1);
    }
#pragma unroll
    for (int mi = 0; mi < 4; mi++) {
        const int r = m0 + wm * 64 + mi * 16 + g;
        float* o0 = out + (size_t)r * OUT_DIM + n0 + wn * 64 + 2 * t;
        float* o1 = o0 + 8 * OUT_DIM;
#pragma unroll
        for (int ni = 0; ni < 8; ni++) {
            *(float2*)(o0 + ni * 8) =
                make_float2(c[mi][ni][0] + bv[ni][0], c[mi][ni][1] + bv[ni][1]);
            *(float2*)(o1 + ni * 8) =
                make_float2(c[mi][ni][2] + bv[ni][0], c[mi][ni][3] + bv[ni][1]);
        }
    }
}

// ---------------------------------------------------------------- launch
extern "C" void kernel_launch(void* const* d_in, const int* in_sizes, int n_in,
                              void* d_out, int out_size) {
    const float* A    = (const float*)d_in[0];
    const float* W    = (const float*)d_in[1];
    const float* bias = (const float*)d_in[2];
    float* out = (float*)d_out;
    (void)in_sizes; (void)n_in; (void)out_size;

    cudaFuncSetAttribute(groupfc_f16_kernel,
                         cudaFuncAttributeMaxDynamicSharedMemorySize, SMEM_TOTAL);

    prep_A_kernel<<<16384, 256>>>(reinterpret_cast<const float4*>(A));
    prep_W_kernel<<<512, 256>>>(reinterpret_cast<const float4*>(W));

    const int grid = (BATCH / BM) * (OUT_DIM / BN);  // 2048
    groupfc_f16_kernel<<<grid, 128, SMEM_TOTAL>>>(bias, out);
}